// round 5
// baseline (speedup 1.0000x reference)
#include <cuda_runtime.h>
#include <cuda_bf16.h>
#include <math.h>
#include <float.h>
#include <stdint.h>

#define S_LEN  2048
#define HID    4096
#define NH     32
#define HD     128
#define QKV_W  12288
#define Q_SIZE 4096
#define KV_SIZE 1024

// ---- GEMM config: CTA 128x128, K chunk 32, 3 cp.async stages ----
#define CHK 32
#define STAGE 32768
#define AH_OFF 0
#define AL_OFF 8192
#define BH_OFF 16384
#define BL_OFF 24576
#define GEMM_SMEM (3 * STAGE)

// ---- Attention config ----
#define BQA 128
#define BKA 64
#define AT_STAGE 65536
#define AT_KH 0
#define AT_KL 16384
#define AT_VH 32768
#define AT_VL 49152
#define AT_QL 131072
#define AT_TAB 163840
#define AT_PQ  172032
#define AT_PK  172544
#define AT_SMEM 173568

// ---------------------------------------------------------------------------
__device__ __align__(256) __nv_bfloat16 g_hs_h[(size_t)S_LEN * HID];
__device__ __align__(256) __nv_bfloat16 g_hs_l[(size_t)S_LEN * HID];
__device__ __align__(256) __nv_bfloat16 g_wqkv_h[(size_t)QKV_W * HID];
__device__ __align__(256) __nv_bfloat16 g_wqkv_l[(size_t)QKV_W * HID];
__device__ __align__(256) __nv_bfloat16 g_wo_h[(size_t)HID * HID];
__device__ __align__(256) __nv_bfloat16 g_wo_l[(size_t)HID * HID];
__device__ __align__(256) __nv_bfloat16 g_qkv_h[(size_t)S_LEN * QKV_W];
__device__ __align__(256) __nv_bfloat16 g_qkv_l[(size_t)S_LEN * QKV_W];
__device__ __align__(256) __nv_bfloat16 g_at_h[(size_t)S_LEN * Q_SIZE];
__device__ __align__(256) __nv_bfloat16 g_at_l[(size_t)S_LEN * Q_SIZE];

// ---------------------------------------------------------------------------
__device__ __forceinline__ uint32_t smem_u32(const void* p) {
    uint32_t a;
    asm("{ .reg .u64 t; cvta.to.shared.u64 t, %1; cvt.u32.u64 %0, t; }"
        : "=r"(a) : "l"(p));
    return a;
}
__device__ __forceinline__ void cpasync16(uint32_t dst, const void* src) {
    asm volatile("cp.async.cg.shared.global [%0], [%1], 16;"
                 :: "r"(dst), "l"(src) : "memory");
}
__device__ __forceinline__ void cpasync4(uint32_t dst, const void* src) {
    asm volatile("cp.async.ca.shared.global [%0], [%1], 4;"
                 :: "r"(dst), "l"(src) : "memory");
}
__device__ __forceinline__ void ldsm4(uint32_t* r, uint32_t addr) {
    asm volatile("ldmatrix.sync.aligned.m8n8.x4.shared.b16 {%0,%1,%2,%3}, [%4];"
                 : "=r"(r[0]), "=r"(r[1]), "=r"(r[2]), "=r"(r[3]) : "r"(addr));
}
__device__ __forceinline__ void ldsm4t(uint32_t* r, uint32_t addr) {
    asm volatile("ldmatrix.sync.aligned.m8n8.x4.trans.shared.b16 {%0,%1,%2,%3}, [%4];"
                 : "=r"(r[0]), "=r"(r[1]), "=r"(r[2]), "=r"(r[3]) : "r"(addr));
}
__device__ __forceinline__ void mma_bf16(float* d, const uint32_t* a,
                                         const uint32_t* b) {
    asm volatile(
        "mma.sync.aligned.m16n8k16.row.col.f32.bf16.bf16.f32 "
        "{%0,%1,%2,%3}, {%4,%5,%6,%7}, {%8,%9}, {%0,%1,%2,%3};"
        : "+f"(d[0]), "+f"(d[1]), "+f"(d[2]), "+f"(d[3])
        : "r"(a[0]), "r"(a[1]), "r"(a[2]), "r"(a[3]), "r"(b[0]), "r"(b[1]));
}
__device__ __forceinline__ uint32_t swz(int row, int seg) {       // 128B rows
    return row * 64 + ((seg ^ ((row >> 1) & 3)) << 4);
}
__device__ __forceinline__ uint32_t swzA(int row, int chunk) {    // 256B rows
    return row * 256 + ((chunk ^ (row & 7)) << 4);
}
// split a float pair into packed bf16x2 hi (trunc) + lo (residual)
__device__ __forceinline__ void split2(float v0, float v1,
                                       uint32_t& hp, uint32_t& lp) {
    uint32_t u0 = __float_as_uint(v0) & 0xFFFF0000u;
    uint32_t u1 = __float_as_uint(v1) & 0xFFFF0000u;
    hp = (u0 >> 16) | u1;
    float r0 = v0 - __uint_as_float(u0);
    float r1 = v1 - __uint_as_float(u1);
    asm("cvt.rn.bf16x2.f32 %0, %1, %2;" : "=r"(lp) : "f"(r1), "f"(r0));
}

// ---------------------------------------------------------------------------
__global__ __launch_bounds__(256) void split_kernel(
    const float* __restrict__ x, __nv_bfloat16* __restrict__ hi,
    __nv_bfloat16* __restrict__ lo, int n)
{
    int i = (blockIdx.x * 256 + threadIdx.x) * 4;
    if (i >= n) return;
    float4 v = *(const float4*)(x + i);
    uint32_t h01, l01, h23, l23;
    split2(v.x, v.y, h01, l01);
    split2(v.z, v.w, h23, l23);
    *(uint2*)(hi + i) = make_uint2(h01, h23);
    *(uint2*)(lo + i) = make_uint2(l01, l23);
}

// ---------------------------------------------------------------------------
// HMMA split-bf16 GEMM NT; MODE 0: fp32 out. MODE 1: hi/lo bf16 out,
// cols < Q_SIZE pre-scaled by 128^-0.5.
// ---------------------------------------------------------------------------
template<int MODE>
__global__ __launch_bounds__(256, 2) void gemm_mma_t(
    const __nv_bfloat16* __restrict__ Ah, const __nv_bfloat16* __restrict__ Al,
    const __nv_bfloat16* __restrict__ Bh, const __nv_bfloat16* __restrict__ Bl,
    float* __restrict__ C, __nv_bfloat16* __restrict__ Ch,
    __nv_bfloat16* __restrict__ Cl, int M, int N, int K)
{
    extern __shared__ __align__(128) char smem_g[];
    const uint32_t sb = smem_u32(smem_g);
    const int tid  = threadIdx.x;
    const int lane = tid & 31, warp = tid >> 5;
    const int wm = warp >> 1, wn = warp & 1;
    const int gid = blockIdx.y * gridDim.x + blockIdx.x;
    const int grp = gid >> 7, loc = gid & 127;     // 128-CTA groups: 8N x 16M
    const int n0 = (grp * 8 + (loc >> 4)) << 7;
    const int m0 = (loc & 15) << 7;
    const int NC = K / CHK;

    const int a_row = lane & 15;
    const int a_kh  = lane >> 4;
    const int b_row = (lane & 7) + ((lane & 16) >> 1);
    const int b_kh  = (lane >> 3) & 1;

    float acc[2][8][4];
#pragma unroll
    for (int mt = 0; mt < 2; mt++)
#pragma unroll
        for (int ng = 0; ng < 8; ng++)
#pragma unroll
            for (int r = 0; r < 4; r++) acc[mt][ng][r] = 0.f;

    auto load_chunk = [&](int c, int s) {
        const uint32_t st = sb + s * STAGE;
        const int k0 = c * CHK;
#pragma unroll
        for (int i = 0; i < 2; i++) {
            int idx = tid + i * 256;
            int row = idx >> 2, seg = idx & 3;
            uint32_t so = swz(row, seg);
            size_t ga = (size_t)(m0 + row) * K + k0 + seg * 8;
            size_t gb = (size_t)(n0 + row) * K + k0 + seg * 8;
            cpasync16(st + AH_OFF + so, Ah + ga);
            cpasync16(st + AL_OFF + so, Al + ga);
            cpasync16(st + BH_OFF + so, Bh + gb);
            cpasync16(st + BL_OFF + so, Bl + gb);
        }
        asm volatile("cp.async.commit_group;" ::: "memory");
    };

    load_chunk(0, 0);
    load_chunk(1, 1);
    load_chunk(2, 2);

    int s = 0;
    for (int c = 0; c < NC; c++) {
        if (c + 2 < NC)
            asm volatile("cp.async.wait_group 2;" ::: "memory");
        else if (c + 1 < NC)
            asm volatile("cp.async.wait_group 1;" ::: "memory");
        else
            asm volatile("cp.async.wait_group 0;" ::: "memory");
        __syncthreads();

        const uint32_t st = sb + s * STAGE;
#pragma unroll
        for (int kk = 0; kk < 2; kk++) {
            uint32_t ah[2][4], al[2][4], bh[4][4], bl[4][4];
#pragma unroll
            for (int mt = 0; mt < 2; mt++)
                ldsm4(ah[mt], st + AH_OFF + swz(wm * 32 + mt * 16 + a_row,
                                                kk * 2 + a_kh));
#pragma unroll
            for (int g = 0; g < 4; g++)
                ldsm4(bh[g], st + BH_OFF + swz(wn * 64 + g * 16 + b_row,
                                               kk * 2 + b_kh));
#pragma unroll
            for (int mt = 0; mt < 2; mt++)
#pragma unroll
                for (int ng = 0; ng < 8; ng++)
                    mma_bf16(acc[mt][ng], ah[mt], &bh[ng >> 1][(ng & 1) * 2]);
#pragma unroll
            for (int g = 0; g < 4; g++)
                ldsm4(bl[g], st + BL_OFF + swz(wn * 64 + g * 16 + b_row,
                                               kk * 2 + b_kh));
#pragma unroll
            for (int mt = 0; mt < 2; mt++)
#pragma unroll
                for (int ng = 0; ng < 8; ng++)
                    mma_bf16(acc[mt][ng], ah[mt], &bl[ng >> 1][(ng & 1) * 2]);
#pragma unroll
            for (int mt = 0; mt < 2; mt++)
                ldsm4(al[mt], st + AL_OFF + swz(wm * 32 + mt * 16 + a_row,
                                                kk * 2 + a_kh));
#pragma unroll
            for (int mt = 0; mt < 2; mt++)
#pragma unroll
                for (int ng = 0; ng < 8; ng++)
                    mma_bf16(acc[mt][ng], al[mt], &bh[ng >> 1][(ng & 1) * 2]);
        }
        __syncthreads();
        if (c + 3 < NC) load_chunk(c + 3, s);
        s = (s == 2) ? 0 : s + 1;
    }

    const int tr = lane >> 2, tc = (lane & 3) * 2;
    const float qsc = 0.08838834764831844f;
#pragma unroll
    for (int mt = 0; mt < 2; mt++) {
        int row = m0 + wm * 32 + mt * 16 + tr;
#pragma unroll
        for (int ng = 0; ng < 8; ng++) {
            int col = n0 + wn * 64 + ng * 8 + tc;
            if (MODE == 0) {
                *(float2*)(C + (size_t)row * N + col) =
                    make_float2(acc[mt][ng][0], acc[mt][ng][1]);
                *(float2*)(C + (size_t)(row + 8) * N + col) =
                    make_float2(acc[mt][ng][2], acc[mt][ng][3]);
            } else {
                float sc = (col < Q_SIZE) ? qsc : 1.f;
                uint32_t hp, lp;
                split2(acc[mt][ng][0] * sc, acc[mt][ng][1] * sc, hp, lp);
                *(uint32_t*)(Ch + (size_t)row * N + col) = hp;
                *(uint32_t*)(Cl + (size_t)row * N + col) = lp;
                split2(acc[mt][ng][2] * sc, acc[mt][ng][3] * sc, hp, lp);
                *(uint32_t*)(Ch + (size_t)(row + 8) * N + col) = hp;
                *(uint32_t*)(Cl + (size_t)(row + 8) * N + col) = lp;
            }
        }
    }
}

// ---------------------------------------------------------------------------
// Tensor-core flash attention: causal + sqrt-ALiBi, split-bf16 3-term MMAs.
// ---------------------------------------------------------------------------
__global__ __launch_bounds__(256, 1) void attn_mma(
    const __nv_bfloat16* __restrict__ qkvh,
    const __nv_bfloat16* __restrict__ qkvl,
    const int* __restrict__ pos,
    __nv_bfloat16* __restrict__ oh, __nv_bfloat16* __restrict__ ol)
{
    extern __shared__ __align__(1024) char sm[];
    const uint32_t sb = smem_u32(sm);
    const int tid = threadIdx.x, lane = tid & 31, w = tid >> 5;
    const int qt = gridDim.x - 1 - blockIdx.x;
    const int h = blockIdx.y, g = h >> 2;
    const int q0 = qt * BQA;
    const float nslope = -exp2f(-0.25f * (float)(h + 1));
    const int qoff = h * HD;
    const int koff = Q_SIZE + g * HD;
    const int voff = Q_SIZE + KV_SIZE + g * HD;
    const int nt = 2 * qt + 2;

    float* tab = (float*)(sm + AT_TAB);
    for (int i = tid; i < 2048; i += 256) tab[i] = sqrtf((float)i);
    if (tid < BQA) ((int*)(sm + AT_PQ))[tid] = pos[q0 + tid];

    // Q hi -> stage0 scratch, Q lo -> persistent region
    for (int i = 0; i < 8; i++) {
        int idx = tid + i * 256;
        int row = idx >> 4, ch = idx & 15;
        size_t go = (size_t)(q0 + row) * QKV_W + qoff + ch * 8;
        cpasync16(sb + swzA(row, ch), qkvh + go);
        cpasync16(sb + AT_QL + swzA(row, ch), qkvl + go);
    }
    asm volatile("cp.async.commit_group;" ::: "memory");
    asm volatile("cp.async.wait_group 0;" ::: "memory");
    __syncthreads();

    const int arow = w * 16 + (lane & 15);
    const int akh = lane >> 4;
    uint32_t qh[8][4];
#pragma unroll
    for (int kk = 0; kk < 8; kk++)
        ldsm4(qh[kk], sb + swzA(arow, kk * 2 + akh));

    const int tr = lane >> 2, c2 = (lane & 3) * 2;
    const int pq0 = ((int*)(sm + AT_PQ))[w * 16 + tr];
    const int pq1 = ((int*)(sm + AT_PQ))[w * 16 + tr + 8];
    const int brow = (lane & 7) + ((lane & 16) >> 1);
    const int bkh = (lane >> 3) & 1;
    const int vrow = lane & 15;
    const int vch = lane >> 4;

    float o[16][4];
#pragma unroll
    for (int j = 0; j < 16; j++)
#pragma unroll
        for (int r = 0; r < 4; r++) o[j][r] = 0.f;
    float mr0 = -1e30f, mr1 = -1e30f, lr0 = 0.f, lr1 = 0.f;
    __syncthreads();   // stage0 scratch free for K/V

    auto issue = [&](int t) {
        int sti = t & 1;
        uint32_t st = sb + sti * AT_STAGE;
        int k0 = t * BKA;
#pragma unroll
        for (int i = 0; i < 4; i++) {
            int idx = tid + i * 256;
            int row = idx >> 4, ch = idx & 15;
            size_t gk = (size_t)(k0 + row) * QKV_W + koff + ch * 8;
            size_t gv = (size_t)(k0 + row) * QKV_W + voff + ch * 8;
            uint32_t so = swzA(row, ch);
            cpasync16(st + AT_KH + so, qkvh + gk);
            cpasync16(st + AT_KL + so, qkvl + gk);
            cpasync16(st + AT_VH + so, qkvh + gv);
            cpasync16(st + AT_VL + so, qkvl + gv);
        }
        if (tid < BKA)
            cpasync4(sb + AT_PK + sti * 256 + tid * 4, pos + k0 + tid);
        asm volatile("cp.async.commit_group;" ::: "memory");
    };

    issue(0);
    for (int t = 0; t < nt; t++) {
        if (t + 1 < nt) {
            issue(t + 1);
            asm volatile("cp.async.wait_group 1;" ::: "memory");
        } else {
            asm volatile("cp.async.wait_group 0;" ::: "memory");
        }
        __syncthreads();

        const uint32_t st = sb + (t & 1) * AT_STAGE;
        const int* pks = (const int*)(sm + AT_PK + (t & 1) * 256);

        // S = Q K^T (3-term)
        float s4[8][4];
#pragma unroll
        for (int ng = 0; ng < 8; ng++)
#pragma unroll
            for (int r = 0; r < 4; r++) s4[ng][r] = 0.f;
#pragma unroll
        for (int kk = 0; kk < 8; kk++) {
            uint32_t kh4[4][4], kl4[4][4], ql4[4];
#pragma unroll
            for (int n16 = 0; n16 < 4; n16++)
                ldsm4(kh4[n16], st + AT_KH + swzA(n16 * 16 + brow, kk * 2 + bkh));
#pragma unroll
            for (int n16 = 0; n16 < 4; n16++)
                ldsm4(kl4[n16], st + AT_KL + swzA(n16 * 16 + brow, kk * 2 + bkh));
            ldsm4(ql4, sb + AT_QL + swzA(arow, kk * 2 + akh));
#pragma unroll
            for (int ng = 0; ng < 8; ng++)
                mma_bf16(s4[ng], qh[kk], &kh4[ng >> 1][(ng & 1) * 2]);
#pragma unroll
            for (int ng = 0; ng < 8; ng++)
                mma_bf16(s4[ng], qh[kk], &kl4[ng >> 1][(ng & 1) * 2]);
#pragma unroll
            for (int ng = 0; ng < 8; ng++)
                mma_bf16(s4[ng], ql4, &kh4[ng >> 1][(ng & 1) * 2]);
        }

        // bias + mask + online softmax
        float mx0 = -FLT_MAX, mx1 = -FLT_MAX;
#pragma unroll
        for (int ng = 0; ng < 8; ng++) {
            int pk0 = pks[ng * 8 + c2], pk1 = pks[ng * 8 + c2 + 1];
            int d00 = pq0 - pk0, d01 = pq0 - pk1;
            int d10 = pq1 - pk0, d11 = pq1 - pk1;
            float v00 = fmaf(nslope, tab[d00 < 0 ? 0 : d00], s4[ng][0]);
            float v01 = fmaf(nslope, tab[d01 < 0 ? 0 : d01], s4[ng][1]);
            float v10 = fmaf(nslope, tab[d10 < 0 ? 0 : d10], s4[ng][2]);
            float v11 = fmaf(nslope, tab[d11 < 0 ? 0 : d11], s4[ng][3]);
            s4[ng][0] = (d00 < 0) ? -FLT_MAX : v00;
            s4[ng][1] = (d01 < 0) ? -FLT_MAX : v01;
            s4[ng][2] = (d10 < 0) ? -FLT_MAX : v10;
            s4[ng][3] = (d11 < 0) ? -FLT_MAX : v11;
            mx0 = fmaxf(mx0, fmaxf(s4[ng][0], s4[ng][1]));
            mx1 = fmaxf(mx1, fmaxf(s4[ng][2], s4[ng][3]));
        }
        mx0 = fmaxf(mx0, __shfl_xor_sync(0xffffffffu, mx0, 1));
        mx0 = fmaxf(mx0, __shfl_xor_sync(0xffffffffu, mx0, 2));
        mx1 = fmaxf(mx1, __shfl_xor_sync(0xffffffffu, mx1, 1));
        mx1 = fmaxf(mx1, __shfl_xor_sync(0xffffffffu, mx1, 2));
        float mn0 = fmaxf(mr0, mx0), mn1 = fmaxf(mr1, mx1);
        float fac0 = __expf(mr0 - mn0), fac1 = __expf(mr1 - mn1);
        mr0 = mn0; mr1 = mn1;

        float sum0 = 0.f, sum1 = 0.f;
        uint32_t pa[4][4], pla[4][4];
#pragma unroll
        for (int ng = 0; ng < 8; ng++) {
            float p0 = __expf(s4[ng][0] - mn0);
            float p1 = __expf(s4[ng][1] - mn0);
            float p2 = __expf(s4[ng][2] - mn1);
            float p3 = __expf(s4[ng][3] - mn1);
            sum0 += p0 + p1;
            sum1 += p2 + p3;
            uint32_t hp01, lp01, hp23, lp23;
            split2(p0, p1, hp01, lp01);
            split2(p2, p3, hp23, lp23);
            int gg = ng >> 1, hf = (ng & 1) * 2;
            pa[gg][hf]      = hp01;
            pa[gg][hf + 1]  = hp23;
            pla[gg][hf]     = lp01;
            pla[gg][hf + 1] = lp23;
        }
        sum0 += __shfl_xor_sync(0xffffffffu, sum0, 1);
        sum0 += __shfl_xor_sync(0xffffffffu, sum0, 2);
        sum1 += __shfl_xor_sync(0xffffffffu, sum1, 1);
        sum1 += __shfl_xor_sync(0xffffffffu, sum1, 2);
        lr0 = lr0 * fac0 + sum0;
        lr1 = lr1 * fac1 + sum1;
#pragma unroll
        for (int j = 0; j < 16; j++) {
            o[j][0] *= fac0; o[j][1] *= fac0;
            o[j][2] *= fac1; o[j][3] *= fac1;
        }

        // O += P V (3-term)
#pragma unroll
        for (int gg = 0; gg < 4; gg++) {
#pragma unroll
            for (int j2 = 0; j2 < 8; j2++) {
                uint32_t vh4[4], vl4[4];
                ldsm4t(vh4, st + AT_VH + swzA(gg * 16 + vrow, j2 * 2 + vch));
                mma_bf16(o[2 * j2],     pa[gg],  &vh4[0]);
                mma_bf16(o[2 * j2 + 1], pa[gg],  &vh4[2]);
                mma_bf16(o[2 * j2],     pla[gg], &vh4[0]);
                mma_bf16(o[2 * j2 + 1], pla[gg], &vh4[2]);
                ldsm4t(vl4, st + AT_VL + swzA(gg * 16 + vrow, j2 * 2 + vch));
                mma_bf16(o[2 * j2],     pa[gg],  &vl4[0]);
                mma_bf16(o[2 * j2 + 1], pa[gg],  &vl4[2]);
            }
        }
        __syncthreads();
    }

    // epilogue: normalize, hi/lo split, store
    float inv0 = 1.f / lr0, inv1 = 1.f / lr1;
    int row0 = q0 + w * 16 + tr, row1 = row0 + 8;
#pragma unroll
    for (int j = 0; j < 16; j++) {
        int col = qoff + j * 8 + c2;
        uint32_t hp, lp;
        split2(o[j][0] * inv0, o[j][1] * inv0, hp, lp);
        *(uint32_t*)(oh + (size_t)row0 * Q_SIZE + col) = hp;
        *(uint32_t*)(ol + (size_t)row0 * Q_SIZE + col) = lp;
        split2(o[j][2] * inv1, o[j][3] * inv1, hp, lp);
        *(uint32_t*)(oh + (size_t)row1 * Q_SIZE + col) = hp;
        *(uint32_t*)(ol + (size_t)row1 * Q_SIZE + col) = lp;
    }
}

// ---------------------------------------------------------------------------
extern "C" void kernel_launch(void* const* d_in, const int* in_sizes, int n_in,
                              void* d_out, int out_size)
{
    (void)in_sizes; (void)n_in; (void)out_size;
    const int*   pos  = (const int*)d_in[0];
    const float* hs   = (const float*)d_in[1];
    const float* wqkv = (const float*)d_in[2];
    const float* wo   = (const float*)d_in[3];
    float* out = (float*)d_out;

    __nv_bfloat16 *hs_h, *hs_l, *wq_h, *wq_l, *wo_h, *wo_l;
    __nv_bfloat16 *qk_h, *qk_l, *at_h, *at_l;
    cudaGetSymbolAddress((void**)&hs_h, g_hs_h);
    cudaGetSymbolAddress((void**)&hs_l, g_hs_l);
    cudaGetSymbolAddress((void**)&wq_h, g_wqkv_h);
    cudaGetSymbolAddress((void**)&wq_l, g_wqkv_l);
    cudaGetSymbolAddress((void**)&wo_h, g_wo_h);
    cudaGetSymbolAddress((void**)&wo_l, g_wo_l);
    cudaGetSymbolAddress((void**)&qk_h, g_qkv_h);
    cudaGetSymbolAddress((void**)&qk_l, g_qkv_l);
    cudaGetSymbolAddress((void**)&at_h, g_at_h);
    cudaGetSymbolAddress((void**)&at_l, g_at_l);

    cudaFuncSetAttribute(gemm_mma_t<0>,
                         cudaFuncAttributeMaxDynamicSharedMemorySize, GEMM_SMEM);
    cudaFuncSetAttribute(gemm_mma_t<1>,
                         cudaFuncAttributeMaxDynamicSharedMemorySize, GEMM_SMEM);
    cudaFuncSetAttribute(attn_mma,
                         cudaFuncAttributeMaxDynamicSharedMemorySize, AT_SMEM);

    split_kernel<<<(S_LEN * HID) / 1024, 256>>>(hs, hs_h, hs_l, S_LEN * HID);
    split_kernel<<<(QKV_W * HID) / 1024, 256>>>(wqkv, wq_h, wq_l, QKV_W * HID);
    split_kernel<<<(HID * HID) / 1024, 256>>>(wo, wo_h, wo_l, HID * HID);

    // 1) QKV projection -> hi/lo bf16 (Q pre-scaled)
    gemm_mma_t<1><<<dim3(QKV_W / 128, S_LEN / 128), 256, GEMM_SMEM>>>(
        hs_h, hs_l, wq_h, wq_l, nullptr, qk_h, qk_l, S_LEN, QKV_W, HID);

    // 2) tensor-core attention -> hi/lo bf16
    attn_mma<<<dim3(S_LEN / BQA, NH), 256, AT_SMEM>>>(qk_h, qk_l, pos,
                                                      at_h, at_l);

    // 3) output projection -> fp32
    gemm_mma_t<0><<<dim3(HID / 128, S_LEN / 128), 256, GEMM_SMEM>>>(
        at_h, at_l, wo_h, wo_l, out, nullptr, nullptr, S_LEN, HID, HID);
}